// round 11
// baseline (speedup 1.0000x reference)
#include <cuda_runtime.h>
#include <cstdint>

#define S_    512
#define P_    196
#define Q_    48
#define CB_   8
#define R_    32
#define C_    10
#define NMID  6

#define THREADS 512

// shared memory layout (floats) — two samples per block.
// Region [0, 18816) is TIME-SHARED: x0/x1 during M phase, G0/G1 during tiles.
#define OFF_XG   0
#define OFF_X0   0            // 9408
#define OFF_X1   9408         // 9408
#define OFF_G0   0            // 8192  G tile s0 [ab(64)][col(128)]
#define OFF_G1   8192         // 8192  G tile s1
#define OFF_M0   18816        // 12544 M s0 [p][ab]
#define OFF_M1   31360        // 12544 M s1
#define OFF_ST   43904        // 2 samples x 2 x 2560 state[a*320+l*10+c]
#define OFF_OUT  54144        // 32
#define SMEM_FLOATS 54176     // 216704 bytes

// M row stride in ulonglong2 units: 64 floats = 16 ulonglong2
#define MSTRIDE 16

__device__ __forceinline__ void ffma2(uint64_t& d, uint64_t a, uint64_t b) {
    asm("fma.rn.f32x2 %0, %1, %2, %0;" : "+l"(d) : "l"(a), "l"(b));
}
__device__ __forceinline__ uint64_t bcast2(float v) {
    uint64_t r; unsigned u = __float_as_uint(v);
    asm("mov.b64 %0, {%1, %1};" : "=l"(r) : "r"(u));
    return r;
}
__device__ __forceinline__ float2 unpack2(uint64_t v) {
    float2 f;
    asm("mov.b64 {%0, %1}, %2;" : "=f"(f.x), "=f"(f.y) : "l"(v));
    return f;
}

// 8 packed-FMA2 for one sample: 8 rows (MA=rows0-3, MB=rows4-7) x 2 cols (B0,B1)
#define FFMA2_P8(ACC, MA, MB, B0, B1)                                  \
    ffma2(ACC[0], MA.x, B0); ffma2(ACC[1], MA.x, B1);                  \
    ffma2(ACC[2], MA.y, B0); ffma2(ACC[3], MA.y, B1);                  \
    ffma2(ACC[4], MB.x, B0); ffma2(ACC[5], MB.x, B1);                  \
    ffma2(ACC[6], MB.y, B0); ffma2(ACC[7], MB.y, B1);

// both samples share the broadcast of av
#define FFMA2_PAIR(A0, M0A, M0B, A1, M1A, M1B, AV)                     \
    {                                                                  \
        uint64_t b0 = bcast2(AV.x), b1 = bcast2(AV.y);                 \
        FFMA2_P8(A0, M0A, M0B, b0, b1)                                 \
        FFMA2_P8(A1, M1A, M1B, b0, b1)                                 \
    }

__global__ void __launch_bounds__(THREADS, 1)
tctl_kernel(const float* __restrict__ x,
            const float* __restrict__ cf,   // [Q][CB]
            const float* __restrict__ cm,   // [NMID][CB][Q][CB]
            const float* __restrict__ cl,   // [CB][Q]
            const float* __restrict__ tf,   // [C][P][R]
            const float* __restrict__ tm,   // [NMID][R][P][R]
            const float* __restrict__ tl,   // [R][P]
            float* __restrict__ out)        // [S][C]
{
    extern __shared__ float smem[];
    float* sx0    = smem + OFF_X0;
    float* sx1    = smem + OFF_X1;
    float* sG0    = smem + OFF_G0;
    float* sG1    = smem + OFF_G1;
    float* sM0    = smem + OFF_M0;
    float* sM1    = smem + OFF_M1;
    float* sState = smem + OFF_ST;
    float* sOut   = smem + OFF_OUT;

    const int tid = threadIdx.x;
    const int s0  = blockIdx.x * 2;
    const int s1  = s0 + 1;
    const float4* xg0 = (const float4*)(x + (size_t)s0 * (P_ * Q_));
    const float4* xg1 = (const float4*)(x + (size_t)s1 * (P_ * Q_));

    // ---------- load both x samples ----------
    for (int i = tid; i < (P_ * Q_) / 4; i += THREADS) {
        ((float4*)sx0)[i] = xg0[i];
        ((float4*)sx1)[i] = xg1[i];
    }
    __syncthreads();

    // ---------- carriage 1: y1[p,b] for both samples (into sM*) ----------
    for (int e = tid; e < 2 * P_ * CB_; e += THREADS) {
        int sh = e >= P_ * CB_;
        int ee = e - sh * (P_ * CB_);
        int p = ee >> 3, b = ee & 7;
        const float* xp = (sh ? sx1 : sx0) + p * Q_;
        float acc = 0.f;
        #pragma unroll
        for (int q = 0; q < Q_; q++) acc += xp[q] * cf[q * 8 + b];
        (sh ? sM1 : sM0)[ee] = acc;
    }
    __syncthreads();

    // state0[b,r,c] = sum_p y1[p,b] * tf[c,p,r]; 512 threads = 2 samples x 256
    {
        const int sh = tid >> 8;
        const int t  = tid & 255;
        const int b = t >> 5, r = t & 31;
        const float* sMs = sh ? sM1 : sM0;
        float acc[C_];
        #pragma unroll
        for (int c = 0; c < C_; c++) acc[c] = 0.f;
        for (int p = 0; p < P_; p++) {
            float y = sMs[p * 8 + b];
            #pragma unroll
            for (int c = 0; c < C_; c++)
                acc[c] += y * tf[((size_t)c * P_ + p) * R_ + r];
        }
        float* st = sState + sh * 5120 + b * 320 + r * 10;
        #pragma unroll
        for (int c = 0; c < C_; c++) st[c] = acc[c];
    }

    // ---------- mid carriages ----------
    // G mapping: 8 row-groups (8 rows) x 64 col-groups (2 cols of 128)
    const int rowGrp = tid >> 6;        // 0..7
    const int colGrp = tid & 63;        // 0..63
    // update mapping: b(8) x r(32) x c-half(2)
    const int bU  = tid >> 6;
    const int rU  = (tid >> 1) & 31;
    const int chU = tid & 1;

    for (int k = 0; k < NMID; k++) {
        const float* Ckg = cm + (size_t)k * (CB_ * Q_ * CB_);
        const float* Ak  = tm + (size_t)k * (R_ * P_ * R_);
        float* stCur0 = sState + (k & 1) * 2560;
        float* stNxt0 = sState + ((k & 1) ^ 1) * 2560;
        float* stCur1 = stCur0 + 5120;
        float* stNxt1 = stNxt0 + 5120;

        __syncthreads();  // prev step fully done (G-region reads finished)

        // reload x (G tiles destroyed it last step)
        if (k > 0) {
            for (int i = tid; i < (P_ * Q_) / 4; i += THREADS) {
                ((float4*)sx0)[i] = xg0[i];
                ((float4*)sx1)[i] = xg1[i];
            }
        }
        __syncthreads();

        // M[p][ab] = sum_q x[p,q]*Ck[a,q,b] for both samples; Ck direct (L1-hot)
        for (int e4 = tid; e4 < 2 * (P_ * 16); e4 += THREADS) {
            int sh = e4 >= P_ * 16;
            int ee = e4 - sh * (P_ * 16);
            int p  = ee >> 4;
            int c4 = ee & 15;
            int a  = c4 >> 1, bq = c4 & 1;
            const float*  xp  = (sh ? sx1 : sx0) + p * Q_;
            const float4* ck4 = (const float4*)(Ckg + a * (Q_ * CB_) + bq * 4);
            float4 acc = make_float4(0.f, 0.f, 0.f, 0.f);
            #pragma unroll
            for (int q = 0; q < Q_; q++) {
                float  f  = xp[q];
                float4 cv = ck4[q * 2];
                acc.x += f * cv.x; acc.y += f * cv.y;
                acc.z += f * cv.z; acc.w += f * cv.w;
            }
            ((float4*)(sh ? sM1 : sM0))[e4 - sh * (P_ * 16)] = acc;
        }

        float ns0[5], ns1[5];
        #pragma unroll
        for (int c = 0; c < 5; c++) { ns0[c] = 0.f; ns1[c] = 0.f; }

        // 8 passes over groups of 4 l-values; per sample G tile [64][128]
        for (int lt = 0; lt < 8; lt++) {
            __syncthreads();  // sM ready (lt=0) / prev pass G reads done

            const int   l   = lt * 4 + (colGrp >> 4);
            const int   r0  = (colGrp & 15) * 2;
            const float* AkL = Ak + (size_t)l * (P_ * R_) + r0;
            const ulonglong2* mb0 = ((const ulonglong2*)sM0) + rowGrp * 2;
            const ulonglong2* mb1 = ((const ulonglong2*)sM1) + rowGrp * 2;

            uint64_t a0[8], a1[8];
            #pragma unroll
            for (int i = 0; i < 8; i++) { a0[i] = 0ull; a1[i] = 0ull; }

            // unroll-2 p loop; av dist-2 prefetch; m dist-1
            float2 av0 = *(const float2*)(AkL + 0 * R_);
            float2 av1 = *(const float2*)(AkL + 1 * R_);
            ulonglong2 m0a = mb0[0], m0b = mb0[1];
            ulonglong2 m1a = mb1[0], m1b = mb1[1];

            #pragma unroll 1
            for (int pb = 0; pb < P_ - 2; pb += 2) {
                float2 avn0 = *(const float2*)(AkL + (pb + 2) * R_);
                ulonglong2 n0a = mb0[(pb + 1) * MSTRIDE];
                ulonglong2 n0b = mb0[(pb + 1) * MSTRIDE + 1];
                ulonglong2 n1a = mb1[(pb + 1) * MSTRIDE];
                ulonglong2 n1b = mb1[(pb + 1) * MSTRIDE + 1];
                FFMA2_PAIR(a0, m0a, m0b, a1, m1a, m1b, av0)

                float2 avn1 = *(const float2*)(AkL + (pb + 3) * R_);
                m0a = mb0[(pb + 2) * MSTRIDE];
                m0b = mb0[(pb + 2) * MSTRIDE + 1];
                m1a = mb1[(pb + 2) * MSTRIDE];
                m1b = mb1[(pb + 2) * MSTRIDE + 1];
                FFMA2_PAIR(a0, n0a, n0b, a1, n1a, n1b, av1)

                av0 = avn0; av1 = avn1;
            }
            // tail: p = 194, 195
            {
                ulonglong2 n0a = mb0[195 * MSTRIDE];
                ulonglong2 n0b = mb0[195 * MSTRIDE + 1];
                ulonglong2 n1a = mb1[195 * MSTRIDE];
                ulonglong2 n1b = mb1[195 * MSTRIDE + 1];
                FFMA2_PAIR(a0, m0a, m0b, a1, m1a, m1b, av0)
                FFMA2_PAIR(a0, n0a, n0b, a1, n1a, n1b, av1)
            }

            // write 8 rows x 2 cols per sample; col pair = (2*colGrp, 2*colGrp+1)
            {
                float2* g20 = (float2*)sG0;
                float2* g21 = (float2*)sG1;
                #pragma unroll
                for (int rp = 0; rp < 4; rp++) {
                    float2 c0 = unpack2(a0[rp * 2 + 0]);
                    float2 c1 = unpack2(a0[rp * 2 + 1]);
                    g20[(rowGrp * 8 + rp * 2 + 0) * 64 + colGrp] = make_float2(c0.x, c1.x);
                    g20[(rowGrp * 8 + rp * 2 + 1) * 64 + colGrp] = make_float2(c0.y, c1.y);
                    float2 d0 = unpack2(a1[rp * 2 + 0]);
                    float2 d1 = unpack2(a1[rp * 2 + 1]);
                    g21[(rowGrp * 8 + rp * 2 + 0) * 64 + colGrp] = make_float2(d0.x, d1.x);
                    g21[(rowGrp * 8 + rp * 2 + 1) * 64 + colGrp] = make_float2(d0.y, d1.y);
                }
            }
            __syncthreads();  // G tiles complete

            // update both samples
            #pragma unroll
            for (int a = 0; a < CB_; a++) {
                #pragma unroll
                for (int lj = 0; lj < 4; lj++) {
                    float g0 = sG0[(a * 8 + bU) * 128 + lj * 32 + rU];
                    float g1 = sG1[(a * 8 + bU) * 128 + lj * 32 + rU];
                    const float* st0 = stCur0 + a * 320 + (lt * 4 + lj) * 10 + chU * 5;
                    const float* st1 = stCur1 + a * 320 + (lt * 4 + lj) * 10 + chU * 5;
                    #pragma unroll
                    for (int c = 0; c < 5; c++) {
                        ns0[c] += st0[c] * g0;
                        ns1[c] += st1[c] * g1;
                    }
                }
            }
        }

        #pragma unroll
        for (int c = 0; c < 5; c++) {
            stNxt0[bU * 320 + rU * 10 + chU * 5 + c] = ns0[c];
            stNxt1[bU * 320 + rU * 10 + chU * 5 + c] = ns1[c];
        }
    }

    // ---------- last carriage ----------
    __syncthreads();   // all G reads done; region reused for x

    for (int i = tid; i < (P_ * Q_) / 4; i += THREADS) {
        ((float4*)sx0)[i] = xg0[i];
        ((float4*)sx1)[i] = xg1[i];
    }
    if (tid < 32) sOut[tid] = 0.f;
    __syncthreads();

    // z[p,a] = sum_q x[p,q] cl[a,q] for both samples (into sM*)
    for (int e = tid; e < 2 * P_ * CB_; e += THREADS) {
        int sh = e >= P_ * CB_;
        int ee = e - sh * (P_ * CB_);
        int p = ee >> 3, a = ee & 7;
        const float* xp  = (sh ? sx1 : sx0) + p * Q_;
        const float* cla = cl + a * Q_;
        float acc = 0.f;
        #pragma unroll
        for (int q = 0; q < Q_; q++) acc += xp[q] * cla[q];
        (sh ? sM1 : sM0)[ee] = acc;
    }
    __syncthreads();

    // GN[a,l] = sum_p z[p,a] tl[l,p];  out[c] = sum_{a,l} state[a,l,c]*GN[a,l]
    {
        const int sh = tid >> 8;
        const int t  = tid & 255;
        const int a = t >> 5, l = t & 31;
        const float* sMs = sh ? sM1 : sM0;
        const float* tlr = tl + l * P_;
        float gn = 0.f;
        for (int p = 0; p < P_; p++) gn += sMs[p * 8 + a] * tlr[p];

        const float* st = sState + sh * 5120 + /*buffer 0*/ a * 320 + l * 10;
        #pragma unroll
        for (int c = 0; c < C_; c++) atomicAdd(&sOut[sh * 16 + c], st[c] * gn);
    }
    __syncthreads();

    if (tid < C_)                    out[(size_t)s0 * C_ + tid]        = sOut[tid];
    else if (tid >= 16 && tid < 16 + C_) out[(size_t)s1 * C_ + (tid - 16)] = sOut[tid];
}

extern "C" void kernel_launch(void* const* d_in, const int* in_sizes, int n_in,
                              void* d_out, int out_size)
{
    const float* x  = (const float*)d_in[0];
    const float* cf = (const float*)d_in[1];
    const float* cm = (const float*)d_in[2];
    const float* cl = (const float*)d_in[3];
    const float* tf = (const float*)d_in[4];
    const float* tm = (const float*)d_in[5];
    const float* tl = (const float*)d_in[6];
    float* out = (float*)d_out;

    size_t shbytes = SMEM_FLOATS * sizeof(float);   // 216704 B
    cudaFuncSetAttribute(tctl_kernel, cudaFuncAttributeMaxDynamicSharedMemorySize,
                         (int)shbytes);
    tctl_kernel<<<S_ / 2, THREADS, shbytes>>>(x, cf, cm, cl, tf, tm, tl, out);
}

// round 12
// speedup vs baseline: 1.4741x; 1.4741x over previous
#include <cuda_runtime.h>
#include <cstdint>

#define S_    512
#define P_    196
#define Q_    48
#define CB_   8
#define R_    32
#define C_    10
#define NMID  6

#define THREADS 512

// shared memory layout (floats)
#define OFF_X   0                      // 9408   x[p][q]
#define OFF_M   9408                   // 12544  M[p][ab]
#define OFF_G   21952                  // 2x8192 G tiles: half A @21952, half B @30144
#define OFF_CK  38336                  // 3072   Ck as [q][a*8+b]
#define OFF_ST  41408                  // 2*2560 state[a*320 + l*10 + c]
#define OFF_OUT 46528                  // 16
#define SMEM_FLOATS 46544

// M row stride in ulonglong2 units: 64 floats = 16 ulonglong2
#define MSTRIDE 16

__device__ __forceinline__ void ffma2(uint64_t& d, uint64_t a, uint64_t b) {
    asm("fma.rn.f32x2 %0, %1, %2, %0;" : "+l"(d) : "l"(a), "l"(b));
}
__device__ __forceinline__ uint64_t add2(uint64_t a, uint64_t b) {
    uint64_t d;
    asm("add.rn.f32x2 %0, %1, %2;" : "=l"(d) : "l"(a), "l"(b));
    return d;
}
__device__ __forceinline__ uint64_t bcast2(float v) {
    uint64_t r; unsigned u = __float_as_uint(v);
    asm("mov.b64 %0, {%1, %1};" : "=l"(r) : "r"(u));
    return r;
}
__device__ __forceinline__ float2 unpack2(uint64_t v) {
    float2 f;
    asm("mov.b64 {%0, %1}, %2;" : "=f"(f.x), "=f"(f.y) : "l"(v));
    return f;
}

// 16 packed-FMA2 block: acc[k*4+j] (+)= (m pair k) * bcast(av lane j)
#define FFMA2_BLOCK(ACC, MA, MB, AV)                                   \
    {                                                                  \
        uint64_t b0 = bcast2(AV.x), b1 = bcast2(AV.y);                 \
        uint64_t b2 = bcast2(AV.z), b3 = bcast2(AV.w);                 \
        ffma2(ACC[0],  MA.x, b0); ffma2(ACC[1],  MA.x, b1);            \
        ffma2(ACC[2],  MA.x, b2); ffma2(ACC[3],  MA.x, b3);            \
        ffma2(ACC[4],  MA.y, b0); ffma2(ACC[5],  MA.y, b1);            \
        ffma2(ACC[6],  MA.y, b2); ffma2(ACC[7],  MA.y, b3);            \
        ffma2(ACC[8],  MB.x, b0); ffma2(ACC[9],  MB.x, b1);            \
        ffma2(ACC[10], MB.x, b2); ffma2(ACC[11], MB.x, b3);            \
        ffma2(ACC[12], MB.y, b0); ffma2(ACC[13], MB.y, b1);            \
        ffma2(ACC[14], MB.y, b2); ffma2(ACC[15], MB.y, b3);            \
    }

__global__ void __launch_bounds__(THREADS, 1)
tctl_kernel(const float* __restrict__ x,
            const float* __restrict__ cf,   // [Q][CB]
            const float* __restrict__ cm,   // [NMID][CB][Q][CB]
            const float* __restrict__ cl,   // [CB][Q]
            const float* __restrict__ tf,   // [C][P][R]
            const float* __restrict__ tm,   // [NMID][R][P][R]
            const float* __restrict__ tl,   // [R][P]
            float* __restrict__ out)        // [S][C]
{
    extern __shared__ float smem[];
    float* sx     = smem + OFF_X;
    float* sM     = smem + OFF_M;
    float* sGall  = smem + OFF_G;
    float* sCk    = smem + OFF_CK;
    float* sState = smem + OFF_ST;
    float* sOut   = smem + OFF_OUT;

    const int tid = threadIdx.x;
    const int s   = blockIdx.x;

    // ---------- load x sample ----------
    {
        const float4* xg = (const float4*)(x + (size_t)s * (P_ * Q_));
        float4* sx4 = (float4*)sx;
        for (int i = tid; i < (P_ * Q_) / 4; i += THREADS) sx4[i] = xg[i];
    }
    for (int i = tid; i < Q_ * CB_; i += THREADS) sCk[i] = cf[i];
    __syncthreads();

    // ---------- carriage 1: y1[p,b] = sum_q x[p,q] cf[q,b] (into sM[p*8+b]) ----------
    for (int e = tid; e < P_ * CB_; e += THREADS) {
        int p = e >> 3, b = e & 7;
        const float* xp = sx + p * Q_;
        float acc = 0.f;
        #pragma unroll
        for (int q = 0; q < Q_; q++) acc += xp[q] * sCk[q * 8 + b];
        sM[e] = acc;
    }
    __syncthreads();

    // state0[b,r,c] = sum_p y1[p,b] * tf[c,p,r]
    if (tid < 256) {
        const int b = tid >> 5, r = tid & 31;
        float acc[C_];
        #pragma unroll
        for (int c = 0; c < C_; c++) acc[c] = 0.f;
        for (int p = 0; p < P_; p++) {
            float y = sM[p * 8 + b];
            #pragma unroll
            for (int c = 0; c < C_; c++)
                acc[c] += y * tf[((size_t)c * P_ + p) * R_ + r];
        }
        #pragma unroll
        for (int c = 0; c < C_; c++) sState[b * 320 + r * 10 + c] = acc[c];
    }

    // ---------- mid carriages: two independent 256-thread halves ----------
    const int h    = tid >> 8;          // 0 or 1 -> l range [h*16, h*16+16)
    const int t    = tid & 255;
    float*    gbuf = sGall + h * 8192;  // this half's 64x128 G tile
    // p-loop mapping within half: 8 rowGrps (8 rows) x 32 colGrps (4 cols of 128)
    const int rowGrp = t >> 5;          // 0..7
    const int colGrp = t & 31;          // 0..31
    // update mapping within half: b(8) x r(32); all 10 c as 5 packed pairs
    const int bU = t >> 5;
    const int rU = t & 31;
    const int barId = h + 1;

    for (int k = 0; k < NMID; k++) {
        const float* Ck = cm + (size_t)k * (CB_ * Q_ * CB_);
        const float* Ak = tm + (size_t)k * (R_ * P_ * R_);
        float* stCur = sState + (k & 1) * 2560;
        float* stNxt = sState + ((k & 1) ^ 1) * 2560;

        __syncthreads();  // stNxt published / scratch+G reads done / sM free

        // Ck -> sCk as [q][a*8+b]
        for (int i = tid; i < CB_ * Q_ * CB_; i += THREADS) {
            int a  = i / (Q_ * CB_);
            int qb = i % (Q_ * CB_);
            int q = qb >> 3, b = qb & 7;
            sCk[q * 64 + a * 8 + b] = Ck[i];
        }
        __syncthreads();

        // M[p][ab] = sum_q x[p,q] * Ck[a,q,b]   (all 512 threads)
        for (int e4 = tid; e4 < (P_ * 64) / 4; e4 += THREADS) {
            int p  = e4 >> 4;
            int c4 = e4 & 15;
            const float*  xp  = sx + p * Q_;
            const float4* ck4 = ((const float4*)sCk) + c4;
            float4 acc = make_float4(0.f, 0.f, 0.f, 0.f);
            #pragma unroll
            for (int q = 0; q < Q_; q++) {
                float  f  = xp[q];
                float4 cv = ck4[q * 16];
                acc.x += f * cv.x; acc.y += f * cv.y;
                acc.z += f * cv.z; acc.w += f * cv.w;
            }
            ((float4*)sM)[e4] = acc;
        }
        __syncthreads();  // sM ready; halves now run decoupled

        uint64_t ns2[5];
        #pragma unroll
        for (int j = 0; j < 5; j++) ns2[j] = 0ull;

        // 4 tiles per half over groups of 4 l-values; tile [64 rows][4*32 cols]
        for (int lt = 0; lt < 4; lt++) {
            const int   tileL = h * 16 + lt * 4;
            const int   l   = tileL + (colGrp >> 3);
            const int   r0  = (colGrp & 7) * 4;
            const float* AkL = Ak + (size_t)l * (P_ * R_) + r0;
            const ulonglong2* mbase = ((const ulonglong2*)sM) + rowGrp * 2;

            uint64_t acc[16];
            #pragma unroll
            for (int i = 0; i < 16; i++) acc[i] = 0ull;

            // unroll-4 p loop, av (LDG.128) prefetched one full body ahead (R7)
            float4 av0 = *(const float4*)(AkL + 0 * R_);
            float4 av1 = *(const float4*)(AkL + 1 * R_);
            float4 av2 = *(const float4*)(AkL + 2 * R_);
            float4 av3 = *(const float4*)(AkL + 3 * R_);
            ulonglong2 ma = mbase[0];
            ulonglong2 mb = mbase[1];

            #pragma unroll 1
            for (int pb = 0; pb < P_ - 4; pb += 4) {
                float4 avn0 = *(const float4*)(AkL + (pb + 4) * R_);
                ulonglong2 ma1 = mbase[(pb + 1) * MSTRIDE];
                ulonglong2 mb1 = mbase[(pb + 1) * MSTRIDE + 1];
                FFMA2_BLOCK(acc, ma, mb, av0)

                float4 avn1 = *(const float4*)(AkL + (pb + 5) * R_);
                ulonglong2 ma2 = mbase[(pb + 2) * MSTRIDE];
                ulonglong2 mb2 = mbase[(pb + 2) * MSTRIDE + 1];
                FFMA2_BLOCK(acc, ma1, mb1, av1)

                float4 avn2 = *(const float4*)(AkL + (pb + 6) * R_);
                ma1 = mbase[(pb + 3) * MSTRIDE];
                mb1 = mbase[(pb + 3) * MSTRIDE + 1];
                FFMA2_BLOCK(acc, ma2, mb2, av2)

                float4 avn3 = *(const float4*)(AkL + (pb + 7) * R_);
                ma = mbase[(pb + 4) * MSTRIDE];
                mb = mbase[(pb + 4) * MSTRIDE + 1];
                FFMA2_BLOCK(acc, ma1, mb1, av3)

                av0 = avn0; av1 = avn1; av2 = avn2; av3 = avn3;
            }
            // tail: p = 192..195 (av0..av3 loaded; ma/mb = row 192)
            {
                ulonglong2 n0 = mbase[193 * MSTRIDE];
                ulonglong2 n1 = mbase[193 * MSTRIDE + 1];
                FFMA2_BLOCK(acc, ma, mb, av0)
                ma = mbase[194 * MSTRIDE];
                mb = mbase[194 * MSTRIDE + 1];
                FFMA2_BLOCK(acc, n0, n1, av1)
                n0 = mbase[195 * MSTRIDE];
                n1 = mbase[195 * MSTRIDE + 1];
                FFMA2_BLOCK(acc, ma, mb, av2)
                FFMA2_BLOCK(acc, n0, n1, av3)
            }

            // write 8 rows x 4 cols to this half's G (row stride 128 fl = 32 f4)
            float4* g4 = (float4*)gbuf;
            #pragma unroll
            for (int kk = 0; kk < 4; kk++) {
                float2 l0 = unpack2(acc[kk * 4 + 0]);
                float2 l1 = unpack2(acc[kk * 4 + 1]);
                float2 l2 = unpack2(acc[kk * 4 + 2]);
                float2 l3 = unpack2(acc[kk * 4 + 3]);
                g4[(rowGrp * 8 + kk * 2 + 0) * 32 + colGrp] =
                    make_float4(l0.x, l1.x, l2.x, l3.x);
                g4[(rowGrp * 8 + kk * 2 + 1) * 32 + colGrp] =
                    make_float4(l0.y, l1.y, l2.y, l3.y);
            }
            asm volatile("bar.sync %0, 256;" :: "r"(barId) : "memory");  // publish

            // ns2[j] (+)= st-pair[j] * bcast(g)  over a(8) x lj(4)
            #pragma unroll
            for (int a = 0; a < CB_; a++) {
                #pragma unroll
                for (int lj = 0; lj < 4; lj++) {
                    float g = gbuf[(a * 8 + bU) * 128 + lj * 32 + rU];
                    uint64_t gb = bcast2(g);
                    const uint64_t* st2 =
                        (const uint64_t*)(stCur + a * 320 + (tileL + lj) * 10);
                    #pragma unroll
                    for (int j = 0; j < 5; j++) ffma2(ns2[j], st2[j], gb);
                }
            }
            asm volatile("bar.sync %0, 256;" :: "r"(barId) : "memory");  // reads done
        }

        // combine halves: A parks partials in its G buffer; B adds and writes stNxt
        if (h == 0) {
            uint64_t* scr = (uint64_t*)(sGall + t * 10);
            #pragma unroll
            for (int j = 0; j < 5; j++) scr[j] = ns2[j];
        }
        __syncthreads();
        if (h == 1) {
            const uint64_t* scr = (const uint64_t*)(sGall + t * 10);
            uint64_t* dst = (uint64_t*)(stNxt + bU * 320 + rU * 10);
            #pragma unroll
            for (int j = 0; j < 5; j++) dst[j] = add2(ns2[j], scr[j]);
        }
    }

    // ---------- last carriage ----------
    __syncthreads();

    // z[p,a] = sum_q x[p,q] cl[a,q]  (into sM[p*8+a])
    for (int e = tid; e < P_ * CB_; e += THREADS) {
        int p = e >> 3, a = e & 7;
        const float* xp  = sx + p * Q_;
        const float* cla = cl + a * Q_;
        float acc = 0.f;
        #pragma unroll
        for (int q = 0; q < Q_; q++) acc += xp[q] * cla[q];
        sM[e] = acc;
    }
    if (tid < C_) sOut[tid] = 0.f;
    __syncthreads();

    // GN[a,l] = sum_p z[p,a] tl[l,p];  out[c] = sum_{a,l} state[a,l,c]*GN[a,l]
    if (tid < 256) {
        const int a = tid >> 5, l = tid & 31;
        const float* tlr = tl + l * P_;
        float gn = 0.f;
        for (int p = 0; p < P_; p++) gn += sM[p * 8 + a] * tlr[p];

        const float* st = sState + /*final buffer 0 (NMID even)*/ a * 320 + l * 10;
        #pragma unroll
        for (int c = 0; c < C_; c++) atomicAdd(&sOut[c], st[c] * gn);
    }
    __syncthreads();

    if (tid < C_) out[(size_t)s * C_ + tid] = sOut[tid];
}

extern "C" void kernel_launch(void* const* d_in, const int* in_sizes, int n_in,
                              void* d_out, int out_size)
{
    const float* x  = (const float*)d_in[0];
    const float* cf = (const float*)d_in[1];
    const float* cm = (const float*)d_in[2];
    const float* cl = (const float*)d_in[3];
    const float* tf = (const float*)d_in[4];
    const float* tm = (const float*)d_in[5];
    const float* tl = (const float*)d_in[6];
    float* out = (float*)d_out;

    size_t shbytes = SMEM_FLOATS * sizeof(float);
    cudaFuncSetAttribute(tctl_kernel, cudaFuncAttributeMaxDynamicSharedMemorySize,
                         (int)shbytes);
    tctl_kernel<<<S_, THREADS, shbytes>>>(x, cf, cm, cl, tf, tm, tl, out);
}